// round 1
// baseline (speedup 1.0000x reference)
#include <cuda_runtime.h>
#include <cstdint>
#include <cstddef>

// ---------------------------------------------------------------------------
// SelectiveViTAdapter: LN(q), LN(f) -> MSDeformAttn -> gamma residual -> stable
// mask-descending sort gather.
//
// Shapes: B=8, D=768, NH=6, DH=128, NP=4, NL=3, LQ=1024, LIN=5376
// Levels: (64,64) start 0, (32,32) start 4096, (16,16) start 5120
// ---------------------------------------------------------------------------

#define BATCH 8
#define DMODEL 768
#define NHEAD 6
#define DHEAD 128
#define NLVL 3
#define NPTS 4
#define LQ 1024
#define LIN 5376
#define NQROWS (BATCH * LQ)      // 8192
#define NFROWS (BATCH * LIN)     // 43008
#define OFFCOLS 144              // NH*NL*NP*2
#define ATTNCOLS 72              // NH*NL*NP

// -------------------- scratch (static device globals; no allocs) -----------
__device__ float g_q[NQROWS * DMODEL];          // 25 MB
__device__ float g_f[NFROWS * DMODEL];          // 132 MB
__device__ float g_value[NFROWS * DMODEL];      // 132 MB
__device__ float g_off[NQROWS * OFFCOLS];
__device__ float g_attnlog[NQROWS * ATTNCOLS];
__device__ float g_samp[NQROWS * DMODEL];       // 25 MB
__device__ float g_attn[NQROWS * DMODEL];       // 25 MB
__device__ int   g_dest[NQROWS];

// -------------------- LayerNorm: one block per row (768 cols) --------------
__global__ void ln_kernel(const float* __restrict__ x,
                          const float* __restrict__ sc,
                          const float* __restrict__ bi,
                          float* __restrict__ y) {
    int row = blockIdx.x;
    int t = threadIdx.x;                      // 256 threads
    const float* xr = x + (size_t)row * DMODEL;
    float v0 = xr[t], v1 = xr[t + 256], v2 = xr[t + 512];
    float sum = v0 + v1 + v2;
    float sq  = v0 * v0 + v1 * v1 + v2 * v2;
    #pragma unroll
    for (int o = 16; o > 0; o >>= 1) {
        sum += __shfl_xor_sync(0xffffffffu, sum, o);
        sq  += __shfl_xor_sync(0xffffffffu, sq,  o);
    }
    __shared__ float ssum[8], ssq[8];
    __shared__ float smean, sinv;
    if ((t & 31) == 0) { ssum[t >> 5] = sum; ssq[t >> 5] = sq; }
    __syncthreads();
    if (t == 0) {
        float S = 0.f, Q = 0.f;
        #pragma unroll
        for (int w = 0; w < 8; w++) { S += ssum[w]; Q += ssq[w]; }
        float mean = S * (1.0f / DMODEL);
        float var  = Q * (1.0f / DMODEL) - mean * mean;
        smean = mean;
        sinv  = rsqrtf(var + 1e-6f);
    }
    __syncthreads();
    float mean = smean, inv = sinv;
    float* yr = y + (size_t)row * DMODEL;
    yr[t]       = (v0 - mean) * inv * sc[t]       + bi[t];
    yr[t + 256] = (v1 - mean) * inv * sc[t + 256] + bi[t + 256];
    yr[t + 512] = (v2 - mean) * inv * sc[t + 512] + bi[t + 512];
}

// -------------------- SGEMM: C[M,N] = A[M,K] @ B[K,N] + bias ---------------
// 128x128 tile, BK=8, 256 threads, 8x8 microtile. Requires M%128==0, K%8==0,
// A/B/C rows 16B-aligned (K,N multiples of 4). N guarded.
#define BM 128
#define BN 128
#define BK 8
__global__ __launch_bounds__(256) void sgemm_kernel(
    const float* __restrict__ A, const float* __restrict__ B,
    const float* __restrict__ bias, float* __restrict__ C,
    int M, int N, int K) {
    __shared__ float As[BK][BM + 4];
    __shared__ float Bs[BK][BN];
    int tid = threadIdx.x;
    int m0 = blockIdx.y * BM;
    int n0 = blockIdx.x * BN;
    int a_r = tid >> 1, a_c = (tid & 1) * 4;      // A: 128 rows x 8 cols
    int b_r = tid >> 5, b_c = (tid & 31) * 4;     // B: 8 rows x 128 cols
    int tx = tid & 15, ty = tid >> 4;
    float acc[8][8];
    #pragma unroll
    for (int i = 0; i < 8; i++)
        #pragma unroll
        for (int j = 0; j < 8; j++) acc[i][j] = 0.f;

    for (int k0 = 0; k0 < K; k0 += BK) {
        float4 av = *(const float4*)(A + (size_t)(m0 + a_r) * K + k0 + a_c);
        As[a_c + 0][a_r] = av.x;
        As[a_c + 1][a_r] = av.y;
        As[a_c + 2][a_r] = av.z;
        As[a_c + 3][a_r] = av.w;
        float4 bv;
        int ncol = n0 + b_c;
        if (ncol + 3 < N) {
            bv = *(const float4*)(B + (size_t)(k0 + b_r) * N + ncol);
        } else {
            const float* brow = B + (size_t)(k0 + b_r) * N;
            bv.x = (ncol + 0 < N) ? brow[ncol + 0] : 0.f;
            bv.y = (ncol + 1 < N) ? brow[ncol + 1] : 0.f;
            bv.z = (ncol + 2 < N) ? brow[ncol + 2] : 0.f;
            bv.w = (ncol + 3 < N) ? brow[ncol + 3] : 0.f;
        }
        *(float4*)&Bs[b_r][b_c] = bv;
        __syncthreads();
        #pragma unroll
        for (int k = 0; k < BK; k++) {
            float ar[8], br[8];
            *(float4*)&ar[0] = *(const float4*)&As[k][ty * 8];
            *(float4*)&ar[4] = *(const float4*)&As[k][ty * 8 + 4];
            *(float4*)&br[0] = *(const float4*)&Bs[k][tx * 8];
            *(float4*)&br[4] = *(const float4*)&Bs[k][tx * 8 + 4];
            #pragma unroll
            for (int i = 0; i < 8; i++)
                #pragma unroll
                for (int j = 0; j < 8; j++)
                    acc[i][j] += ar[i] * br[j];
        }
        __syncthreads();
    }

    int mrow = m0 + ty * 8;
    int ncol = n0 + tx * 8;
    #pragma unroll
    for (int i = 0; i < 8; i++) {
        float* crow = C + (size_t)(mrow + i) * N;
        if (ncol + 7 < N) {
            float4 o0, o1;
            o0.x = acc[i][0] + bias[ncol + 0];
            o0.y = acc[i][1] + bias[ncol + 1];
            o0.z = acc[i][2] + bias[ncol + 2];
            o0.w = acc[i][3] + bias[ncol + 3];
            o1.x = acc[i][4] + bias[ncol + 4];
            o1.y = acc[i][5] + bias[ncol + 5];
            o1.z = acc[i][6] + bias[ncol + 6];
            o1.w = acc[i][7] + bias[ncol + 7];
            *(float4*)(crow + ncol)     = o0;
            *(float4*)(crow + ncol + 4) = o1;
        } else {
            #pragma unroll
            for (int j = 0; j < 8; j++) {
                int n = ncol + j;
                if (n < N) crow[n] = acc[i][j] + bias[n];
            }
        }
    }
}

// -------------------- MSDeformAttn sampling --------------------------------
// One block (128 threads) per (b, q). Thread = channel d in [0,128).
__global__ __launch_bounds__(128) void msda_sample_kernel(
    const float* __restrict__ off,
    const float* __restrict__ logits,
    const float* __restrict__ value,
    float* __restrict__ out) {
    __shared__ float sl[72];
    __shared__ float saw[72];
    __shared__ int   srow[72][4];
    __shared__ float swgt[72][4];

    int row = blockIdx.x;                 // b*LQ + q
    int b = row >> 10, q = row & 1023;
    int t = threadIdx.x;

    if (t < 72) sl[t] = logits[(size_t)row * ATTNCOLS + t];
    __syncthreads();

    if (t < 6) {   // per-head softmax over 12 points
        float mx = -1e30f;
        #pragma unroll
        for (int s = 0; s < 12; s++) mx = fmaxf(mx, sl[t * 12 + s]);
        float e[12], sum = 0.f;
        #pragma unroll
        for (int s = 0; s < 12; s++) { e[s] = expf(sl[t * 12 + s] - mx); sum += e[s]; }
        float inv = 1.f / sum;
        #pragma unroll
        for (int s = 0; s < 12; s++) saw[t * 12 + s] = e[s] * inv;
    }
    __syncthreads();

    if (t < 72) {  // per-(head,level,point) sample metadata
        int h = t / 12, s = t % 12, lvl = s >> 2, p = s & 3;
        const int DIMS[3] = {64, 32, 16};
        const int ST[3]   = {0, 4096, 5120};
        int Hd = DIMS[lvl], Wd = DIMS[lvl], st = ST[lvl];
        float refx = ((q & 31) + 0.5f) * (1.0f / 32.0f);
        float refy = ((q >> 5) + 0.5f) * (1.0f / 32.0f);
        size_t obase = (size_t)row * OFFCOLS + h * 24 + lvl * 8 + p * 2;
        float ox = off[obase + 0];
        float oy = off[obase + 1];
        float lx = refx + ox / (float)Wd;
        float ly = refy + oy / (float)Hd;
        float x = lx * (float)Wd - 0.5f;
        float y = ly * (float)Hd - 0.5f;
        float x0 = floorf(x), y0 = floorf(y);
        float wx1 = x - x0, wy1 = y - y0;
        int x0i = (int)x0, y0i = (int)y0;
        float aw = saw[t];
        #pragma unroll
        for (int c = 0; c < 4; c++) {
            int dx = c & 1, dy = c >> 1;
            int xi = x0i + dx, yi = y0i + dy;
            bool valid = (xi >= 0) && (xi < Wd) && (yi >= 0) && (yi < Hd);
            float wx = dx ? wx1 : 1.f - wx1;
            float wy = dy ? wy1 : 1.f - wy1;
            srow[t][c] = valid ? (st + yi * Wd + xi) : -1;
            swgt[t][c] = aw * wx * wy;
        }
    }
    __syncthreads();

    int d = t;  // channel
    const float* vb = value + (size_t)b * LIN * DMODEL + d;
    float* orow = out + (size_t)row * DMODEL + d;
    #pragma unroll 1
    for (int h = 0; h < NHEAD; h++) {
        float acc = 0.f;
        const float* vh = vb + h * DHEAD;
        #pragma unroll 1
        for (int s = 0; s < 12; s++) {
            int tt = h * 12 + s;
            #pragma unroll
            for (int c = 0; c < 4; c++) {
                int r = srow[tt][c];
                if (r >= 0) acc += swgt[tt][c] * vh[(size_t)r * DMODEL];
            }
        }
        orow[h * DHEAD] = acc;
    }
}

// -------------------- stable mask-descending destinations ------------------
// One block (1024 threads) per batch. Fingerprints the mask dtype from the
// first 8192 bytes (safe under uint8 / int32 / float32 interpretations).
__global__ void dest_kernel(const void* __restrict__ mraw, int* __restrict__ dest) {
    __shared__ int flagA, flagB;
    __shared__ int s[1024];
    int b = blockIdx.x, i = threadIdx.x;
    const unsigned char* mb = (const unsigned char*)mraw;
    if (i == 0) { flagA = 0; flagB = 0; }
    __syncthreads();
    int la = 0, lb = 0;
    for (int j = i; j < 8192; j += 1024) {
        if (mb[j]) { if ((j & 3) == 0) la = 1; else lb = 1; }
    }
    if (la) atomicOr(&flagA, 1);
    if (lb) atomicOr(&flagB, 1);
    __syncthreads();
    int a = flagA, bb = flagB;
    int idx = (b << 10) + i;
    int m;
    if (a && !bb)        m = (((const int*)mraw)[idx] != 0);        // int32 0/1
    else if (!a && bb)   m = (((const float*)mraw)[idx] != 0.0f);   // float32 0/1
    else                 m = (mb[idx] != 0);                        // uint8 bool
    s[i] = m;
    __syncthreads();
    for (int off = 1; off < 1024; off <<= 1) {
        int v = (i >= off) ? s[i - off] : 0;
        __syncthreads();
        s[i] += v;
        __syncthreads();
    }
    int incl = s[i];
    int T = s[1023];
    int excl = incl - m;
    dest[idx] = m ? excl : (T + i - excl);
}

// -------------------- residual + scatter -----------------------------------
__global__ void final_kernel(const float* __restrict__ query,
                             const float* __restrict__ gamma,
                             const float* __restrict__ attn,
                             const int* __restrict__ dest,
                             float* __restrict__ out) {
    int row = blockIdx.x;                // b*LQ + i
    int b = row >> 10;
    int dst = dest[row];
    const float* qr = query + (size_t)row * DMODEL;
    const float* ar = attn + (size_t)row * DMODEL;
    float* orow = out + ((size_t)(b << 10) + dst) * DMODEL;
    for (int c = threadIdx.x; c < DMODEL; c += blockDim.x)
        orow[c] = qr[c] + gamma[c] * ar[c];
}

// -------------------- launch -----------------------------------------------
extern "C" void kernel_launch(void* const* d_in, const int* in_sizes, int n_in,
                              void* d_out, int out_size) {
    const float* query  = (const float*)d_in[0];
    const float* feat   = (const float*)d_in[1];
    const void*  mask   = d_in[2];
    const float* ln_q_s = (const float*)d_in[3];
    const float* ln_q_b = (const float*)d_in[4];
    const float* ln_f_s = (const float*)d_in[5];
    const float* ln_f_b = (const float*)d_in[6];
    const float* W_val  = (const float*)d_in[7];
    const float* b_val  = (const float*)d_in[8];
    const float* W_off  = (const float*)d_in[9];
    const float* b_off  = (const float*)d_in[10];
    const float* W_attn = (const float*)d_in[11];
    const float* b_attn = (const float*)d_in[12];
    const float* W_out  = (const float*)d_in[13];
    const float* b_out  = (const float*)d_in[14];
    const float* gamma  = (const float*)d_in[15];
    float* out = (float*)d_out;

    float *q_s, *f_s, *val_s, *off_s, *al_s, *samp_s, *attn_s;
    int* dest_s;
    cudaGetSymbolAddress((void**)&q_s,    g_q);
    cudaGetSymbolAddress((void**)&f_s,    g_f);
    cudaGetSymbolAddress((void**)&val_s,  g_value);
    cudaGetSymbolAddress((void**)&off_s,  g_off);
    cudaGetSymbolAddress((void**)&al_s,   g_attnlog);
    cudaGetSymbolAddress((void**)&samp_s, g_samp);
    cudaGetSymbolAddress((void**)&attn_s, g_attn);
    cudaGetSymbolAddress((void**)&dest_s, g_dest);

    ln_kernel<<<NQROWS, 256>>>(query, ln_q_s, ln_q_b, q_s);
    ln_kernel<<<NFROWS, 256>>>(feat,  ln_f_s, ln_f_b, f_s);

    // value = f @ W_val + b_val     (43008 x 768 x 768)
    sgemm_kernel<<<dim3(DMODEL / BN, NFROWS / BM), 256>>>(
        f_s, W_val, b_val, val_s, NFROWS, DMODEL, DMODEL);
    // off = q @ W_off + b_off       (8192 x 144 x 768)
    sgemm_kernel<<<dim3((OFFCOLS + BN - 1) / BN, NQROWS / BM), 256>>>(
        q_s, W_off, b_off, off_s, NQROWS, OFFCOLS, DMODEL);
    // attn logits = q @ W_attn + b_attn (8192 x 72 x 768)
    sgemm_kernel<<<dim3((ATTNCOLS + BN - 1) / BN, NQROWS / BM), 256>>>(
        q_s, W_attn, b_attn, al_s, NQROWS, ATTNCOLS, DMODEL);

    msda_sample_kernel<<<NQROWS, 128>>>(off_s, al_s, val_s, samp_s);

    // attn = samp @ W_out + b_out   (8192 x 768 x 768)
    sgemm_kernel<<<dim3(DMODEL / BN, NQROWS / BM), 256>>>(
        samp_s, W_out, b_out, attn_s, NQROWS, DMODEL, DMODEL);

    dest_kernel<<<BATCH, 1024>>>(mask, dest_s);
    final_kernel<<<NQROWS, 256>>>(query, gamma, attn_s, dest_s, out);
}

// round 6
// speedup vs baseline: 4.4722x; 4.4722x over previous
#include <cuda_runtime.h>
#include <cuda_bf16.h>
#include <cstdint>
#include <cstddef>

// ---------------------------------------------------------------------------
// SelectiveViTAdapter: LN(q), LN(f) -> MSDeformAttn -> gamma residual -> stable
// mask-descending sort gather.
// GEMMs: classic tensor-core path (ldmatrix + mma.sync m16n8k16 bf16, fp32 acc),
// cp.async double-buffered feeds. No tcgen05 / no mbarrier / static smem only.
//
// Shapes: B=8, D=768, NH=6, DH=128, NP=4, NL=3, LQ=1024, LIN=5376
// ---------------------------------------------------------------------------

#define BATCH 8
#define DMODEL 768
#define NHEAD 6
#define DHEAD 128
#define LQ 1024
#define LIN 5376
#define NQROWS (BATCH * LQ)      // 8192
#define NFROWS (BATCH * LIN)     // 43008
#define OFFCOLS 144              // real cols of off GEMM
#define ATTNCOLS 72              // real cols of attn-logit GEMM
#define OFF_LD 256               // padded stride
#define ATT_LD 128               // padded stride

// -------------------- scratch (static device globals) ----------------------
__device__ __nv_bfloat16 g_qbf[NQROWS * DMODEL];
__device__ __nv_bfloat16 g_fbf[NFROWS * DMODEL];
__device__ float         g_value[NFROWS * DMODEL];
__device__ float         g_off[NQROWS * OFF_LD];
__device__ float         g_attnlog[NQROWS * ATT_LD];
__device__ __nv_bfloat16 g_sampb[NQROWS * DMODEL];
__device__ float         g_attn[NQROWS * DMODEL];
__device__ int           g_dest[NQROWS];
__device__ __nv_bfloat16 g_wvalT[DMODEL * DMODEL];
__device__ __nv_bfloat16 g_woutT[DMODEL * DMODEL];
__device__ __nv_bfloat16 g_woffT[OFF_LD * DMODEL];
__device__ __nv_bfloat16 g_wattnT[ATT_LD * DMODEL];

// -------------------- PTX helpers ------------------------------------------
__device__ __forceinline__ uint32_t smem_u32(const void* p) {
    uint32_t a;
    asm("{ .reg .u64 t; cvta.to.shared.u64 t, %1; cvt.u32.u64 %0, t; }" : "=r"(a) : "l"(p));
    return a;
}
#define CP_ASYNC16(dst, src) asm volatile("cp.async.cg.shared.global [%0], [%1], 16;" :: "r"(dst), "l"(src) : "memory")
#define CP_COMMIT()          asm volatile("cp.async.commit_group;" ::: "memory")
#define CP_WAIT(n)           asm volatile("cp.async.wait_group %0;" :: "n"(n) : "memory")
#define LDSM4(r, a) asm volatile("ldmatrix.sync.aligned.m8n8.x4.shared.b16 {%0,%1,%2,%3}, [%4];" \
    : "=r"((r)[0]), "=r"((r)[1]), "=r"((r)[2]), "=r"((r)[3]) : "r"(a))

__device__ __forceinline__ void mma16816(float* c, const uint32_t* a, uint32_t b0, uint32_t b1) {
    asm volatile(
        "mma.sync.aligned.m16n8k16.row.col.f32.bf16.bf16.f32 "
        "{%0,%1,%2,%3}, {%4,%5,%6,%7}, {%8,%9}, {%0,%1,%2,%3};"
        : "+f"(c[0]), "+f"(c[1]), "+f"(c[2]), "+f"(c[3])
        : "r"(a[0]), "r"(a[1]), "r"(a[2]), "r"(a[3]), "r"(b0), "r"(b1));
}

// Swizzled smem offset for a [rows x 32 bf16] tile (64B rows, 16B chunks):
// conflict-free ldmatrix across any aligned 8-row group.
__device__ __forceinline__ uint32_t sw_off(int r, int c) {
    return (uint32_t)(r * 64 + ((c ^ ((r >> 1) & 3)) << 4));
}

// -------------------- bf16 tensor-core GEMM --------------------------------
// C[m0:m0+128, n0:n0+128] = A[m0:, :768] @ Bt[n0:, :768]^T + bias
// A bf16 [M,768] row-major; Bt bf16 [Npad,768] row-major (pre-transposed,
// zero-padded). 256 threads, 8 warps (2x4), warp tile 64x32, BK=32,
// double-buffered cp.async. Static smem 32KB.
__global__ __launch_bounds__(256) void mma_gemm(
    const __nv_bfloat16* __restrict__ A, const __nv_bfloat16* __restrict__ Bt,
    const float* __restrict__ bias, float* __restrict__ C,
    int Nreal, int ldc) {
    __shared__ __align__(128) char smbuf[2 * 16384];   // stage: A 8K + B 8K
    uint32_t sb = smem_u32(smbuf);
    int tid = threadIdx.x, wid = tid >> 5, lane = tid & 31;
    int m0 = blockIdx.y * 128, n0 = blockIdx.x * 128;
    int wm = (wid >> 2) * 64, wn = (wid & 3) * 32;

    const __nv_bfloat16* Ag = A + (size_t)m0 * DMODEL;
    const __nv_bfloat16* Bg = Bt + (size_t)n0 * DMODEL;

    // per-thread load coords: each operand tile = 512 x 16B chunks, 2/thread
    int lr0 = tid >> 2, lc = tid & 3;          // rows 0..63
    int lr1 = lr0 + 64;                        // rows 64..127
    uint32_t dA0 = sw_off(lr0, lc), dA1 = sw_off(lr1, lc);

    float acc[4][4][4];
    #pragma unroll
    for (int i = 0; i < 4; i++)
        #pragma unroll
        for (int j = 0; j < 4; j++)
            #pragma unroll
            for (int k = 0; k < 4; k++) acc[i][j][k] = 0.f;

    // prologue: tile 0 -> stage 0
    {
        int k0 = 0;
        CP_ASYNC16(sb + dA0,        Ag + (size_t)lr0 * DMODEL + k0 + lc * 8);
        CP_ASYNC16(sb + dA1,        Ag + (size_t)lr1 * DMODEL + k0 + lc * 8);
        CP_ASYNC16(sb + 8192 + dA0, Bg + (size_t)lr0 * DMODEL + k0 + lc * 8);
        CP_ASYNC16(sb + 8192 + dA1, Bg + (size_t)lr1 * DMODEL + k0 + lc * 8);
        CP_COMMIT();
    }

    for (int it = 0; it < 24; ++it) {
        if (it + 1 < 24) {
            uint32_t stg = sb + ((it + 1) & 1) * 16384;
            int k0 = (it + 1) * 32;
            CP_ASYNC16(stg + dA0,        Ag + (size_t)lr0 * DMODEL + k0 + lc * 8);
            CP_ASYNC16(stg + dA1,        Ag + (size_t)lr1 * DMODEL + k0 + lc * 8);
            CP_ASYNC16(stg + 8192 + dA0, Bg + (size_t)lr0 * DMODEL + k0 + lc * 8);
            CP_ASYNC16(stg + 8192 + dA1, Bg + (size_t)lr1 * DMODEL + k0 + lc * 8);
            CP_COMMIT();
            CP_WAIT(1);
        } else {
            CP_WAIT(0);
        }
        __syncthreads();

        uint32_t aB = sb + (it & 1) * 16384;
        uint32_t bB = aB + 8192;
        #pragma unroll
        for (int ks = 0; ks < 2; ks++) {
            uint32_t ar[4][4], br[2][4];
            #pragma unroll
            for (int mi = 0; mi < 4; mi++) {
                int row = wm + mi * 16 + (lane & 15);
                int c = ks * 2 + (lane >> 4);
                LDSM4(ar[mi], aB + sw_off(row, c));
            }
            #pragma unroll
            for (int nb = 0; nb < 2; nb++) {
                int row = wn + nb * 16 + (lane & 7) + ((lane & 16) >> 1);
                int c = ks * 2 + ((lane & 8) >> 3);
                LDSM4(br[nb], bB + sw_off(row, c));
            }
            #pragma unroll
            for (int mi = 0; mi < 4; mi++)
                #pragma unroll
                for (int ni = 0; ni < 4; ni++)
                    mma16816(acc[mi][ni], ar[mi],
                             br[ni >> 1][(ni & 1) * 2], br[ni >> 1][(ni & 1) * 2 + 1]);
        }
        __syncthreads();
    }

    // epilogue: fragment layout c0,c1 -> (row, col..col+1); c2,c3 -> (row+8, ..)
    #pragma unroll
    for (int mi = 0; mi < 4; mi++) {
        int row = m0 + wm + mi * 16 + (lane >> 2);
        #pragma unroll
        for (int ni = 0; ni < 4; ni++) {
            int col = n0 + wn + ni * 8 + (lane & 3) * 2;
            float b0 = (col < Nreal) ? bias[col] : 0.f;
            float b1 = (col + 1 < Nreal) ? bias[col + 1] : 0.f;
            float2 v0 = { acc[mi][ni][0] + b0, acc[mi][ni][1] + b1 };
            float2 v1 = { acc[mi][ni][2] + b0, acc[mi][ni][3] + b1 };
            *(float2*)(C + (size_t)row * ldc + col) = v0;
            *(float2*)(C + (size_t)(row + 8) * ldc + col) = v1;
        }
    }
}

// -------------------- weight transpose+pad: Wt[n][k] = W[k][n] (bf16) ------
__global__ void transpose_pad(const float* __restrict__ W, __nv_bfloat16* __restrict__ Wt,
                              int N, int Npad) {
    int k = blockIdx.x * 256 + threadIdx.x;   // grid.x = 3 -> k in [0,768)
    int n = blockIdx.y;                        // grid.y = Npad
    float v = (n < N) ? W[(size_t)k * N + n] : 0.f;
    Wt[(size_t)n * DMODEL + k] = __float2bfloat16(v);
}

// -------------------- LayerNorm (f32 in -> bf16 out) -----------------------
__global__ void ln_kernel(const float* __restrict__ x,
                          const float* __restrict__ sc,
                          const float* __restrict__ bi,
                          __nv_bfloat16* __restrict__ y) {
    int row = blockIdx.x;
    int t = threadIdx.x;                       // 256 threads
    const float* xr = x + (size_t)row * DMODEL;
    float v0 = xr[t], v1 = xr[t + 256], v2 = xr[t + 512];
    float sum = v0 + v1 + v2;
    float sq  = v0 * v0 + v1 * v1 + v2 * v2;
    #pragma unroll
    for (int o = 16; o > 0; o >>= 1) {
        sum += __shfl_xor_sync(0xffffffffu, sum, o);
        sq  += __shfl_xor_sync(0xffffffffu, sq,  o);
    }
    __shared__ float ssum[8], ssq[8];
    __shared__ float smean, sinv;
    if ((t & 31) == 0) { ssum[t >> 5] = sum; ssq[t >> 5] = sq; }
    __syncthreads();
    if (t == 0) {
        float S = 0.f, Q = 0.f;
        #pragma unroll
        for (int w = 0; w < 8; w++) { S += ssum[w]; Q += ssq[w]; }
        float mean = S * (1.0f / DMODEL);
        float var  = Q * (1.0f / DMODEL) - mean * mean;
        smean = mean;
        sinv  = rsqrtf(var + 1e-6f);
    }
    __syncthreads();
    float mean = smean, inv = sinv;
    __nv_bfloat16* yr = y + (size_t)row * DMODEL;
    yr[t]       = __float2bfloat16((v0 - mean) * inv * sc[t]       + bi[t]);
    yr[t + 256] = __float2bfloat16((v1 - mean) * inv * sc[t + 256] + bi[t + 256]);
    yr[t + 512] = __float2bfloat16((v2 - mean) * inv * sc[t + 512] + bi[t + 512]);
}

// -------------------- MSDeformAttn sampling --------------------------------
// One block (128 threads) per (b, q). Thread = channel d in [0,128).
__global__ __launch_bounds__(128) void msda_sample_kernel(
    const float* __restrict__ off,      // [NQROWS, OFF_LD]
    const float* __restrict__ logits,   // [NQROWS, ATT_LD]
    const float* __restrict__ value,    // [NFROWS, 768] f32
    __nv_bfloat16* __restrict__ out) {  // [NQROWS, 768] bf16
    __shared__ float sl[72];
    __shared__ float saw[72];
    __shared__ int   srow[72][4];
    __shared__ float swgt[72][4];

    int row = blockIdx.x;
    int b = row >> 10, q = row & 1023;
    int t = threadIdx.x;

    if (t < 72) sl[t] = logits[(size_t)row * ATT_LD + t];
    __syncthreads();

    if (t < 6) {
        float mx = -1e30f;
        #pragma unroll
        for (int s = 0; s < 12; s++) mx = fmaxf(mx, sl[t * 12 + s]);
        float e[12], sum = 0.f;
        #pragma unroll
        for (int s = 0; s < 12; s++) { e[s] = expf(sl[t * 12 + s] - mx); sum += e[s]; }
        float inv = 1.f / sum;
        #pragma unroll
        for (int s = 0; s < 12; s++) saw[t * 12 + s] = e[s] * inv;
    }
    __syncthreads();

    if (t < 72) {
        int h = t / 12, s = t % 12, lvl = s >> 2, p = s & 3;
        const int DIMS[3] = {64, 32, 16};
        const int ST[3]   = {0, 4096, 5120};
        int Hd = DIMS[lvl], Wd = DIMS[lvl], st = ST[lvl];
        float refx = ((q & 31) + 0.5f) * (1.0f / 32.0f);
        float refy = ((q >> 5) + 0.5f) * (1.0f / 32.0f);
        size_t obase = (size_t)row * OFF_LD + h * 24 + lvl * 8 + p * 2;
        float ox = off[obase + 0];
        float oy = off[obase + 1];
        float x = (refx + ox / (float)Wd) * (float)Wd - 0.5f;
        float y = (refy + oy / (float)Hd) * (float)Hd - 0.5f;
        float x0 = floorf(x), y0 = floorf(y);
        float wx1 = x - x0, wy1 = y - y0;
        int x0i = (int)x0, y0i = (int)y0;
        float aw = saw[t];
        #pragma unroll
        for (int c = 0; c < 4; c++) {
            int dx = c & 1, dy = c >> 1;
            int xi = x0i + dx, yi = y0i + dy;
            bool valid = (xi >= 0) && (xi < Wd) && (yi >= 0) && (yi < Hd);
            float wx = dx ? wx1 : 1.f - wx1;
            float wy = dy ? wy1 : 1.f - wy1;
            srow[t][c] = valid ? (st + yi * Wd + xi) : -1;
            swgt[t][c] = aw * wx * wy;
        }
    }
    __syncthreads();

    int d = t;
    const float* vb = value + (size_t)b * LIN * DMODEL + d;
    __nv_bfloat16* orow = out + (size_t)row * DMODEL + d;
    #pragma unroll 1
    for (int h = 0; h < NHEAD; h++) {
        float acc = 0.f;
        const float* vh = vb + h * DHEAD;
        #pragma unroll 1
        for (int s = 0; s < 12; s++) {
            int tt = h * 12 + s;
            #pragma unroll
            for (int c = 0; c < 4; c++) {
                int r = srow[tt][c];
                if (r >= 0) acc += swgt[tt][c] * vh[(size_t)r * DMODEL];
            }
        }
        orow[h * DHEAD] = __float2bfloat16(acc);
    }
}

// -------------------- stable mask-descending destinations ------------------
__global__ void dest_kernel(const void* __restrict__ mraw, int* __restrict__ dest) {
    __shared__ int flagA, flagB;
    __shared__ int s[1024];
    int b = blockIdx.x, i = threadIdx.x;
    const unsigned char* mb = (const unsigned char*)mraw;
    if (i == 0) { flagA = 0; flagB = 0; }
    __syncthreads();
    int la = 0, lb = 0;
    for (int j = i; j < 8192; j += 1024) {
        if (mb[j]) { if ((j & 3) == 0) la = 1; else lb = 1; }
    }
    if (la) atomicOr(&flagA, 1);
    if (lb) atomicOr(&flagB, 1);
    __syncthreads();
    int a = flagA, bb = flagB;
    int idx = (b << 10) + i;
    int m;
    if (a && !bb)        m = (((const int*)mraw)[idx] != 0);
    else if (!a && bb)   m = (((const float*)mraw)[idx] != 0.0f);
    else                 m = (mb[idx] != 0);
    s[i] = m;
    __syncthreads();
    for (int off = 1; off < 1024; off <<= 1) {
        int v = (i >= off) ? s[i - off] : 0;
        __syncthreads();
        s[i] += v;
        __syncthreads();
    }
    int incl = s[i];
    int T = s[1023];
    int excl = incl - m;
    dest[idx] = m ? excl : (T + i - excl);
}

// -------------------- residual + scatter -----------------------------------
__global__ void final_kernel(const float* __restrict__ query,
                             const float* __restrict__ gamma,
                             const float* __restrict__ attn,
                             const int* __restrict__ dest,
                             float* __restrict__ out) {
    int row = blockIdx.x;
    int b = row >> 10;
    int dst = dest[row];
    const float* qr = query + (size_t)row * DMODEL;
    const float* ar = attn + (size_t)row * DMODEL;
    float* orow = out + ((size_t)(b << 10) + dst) * DMODEL;
    for (int c = threadIdx.x; c < DMODEL; c += blockDim.x)
        orow[c] = qr[c] + gamma[c] * ar[c];
}

// -------------------- launch -----------------------------------------------
extern "C" void kernel_launch(void* const* d_in, const int* in_sizes, int n_in,
                              void* d_out, int out_size) {
    const float* query  = (const float*)d_in[0];
    const float* feat   = (const float*)d_in[1];
    const void*  mask   = d_in[2];
    const float* ln_q_s = (const float*)d_in[3];
    const float* ln_q_b = (const float*)d_in[4];
    const float* ln_f_s = (const float*)d_in[5];
    const float* ln_f_b = (const float*)d_in[6];
    const float* W_val  = (const float*)d_in[7];
    const float* b_val  = (const float*)d_in[8];
    const float* W_off  = (const float*)d_in[9];
    const float* b_off  = (const float*)d_in[10];
    const float* W_attn = (const float*)d_in[11];
    const float* b_attn = (const float*)d_in[12];
    const float* W_out  = (const float*)d_in[13];
    const float* b_out  = (const float*)d_in[14];
    const float* gamma  = (const float*)d_in[15];
    float* out = (float*)d_out;

    __nv_bfloat16 *qbf, *fbf, *sampb, *wvalT, *woutT, *woffT, *wattnT;
    float *val_s, *off_s, *al_s, *attn_s;
    int* dest_s;
    cudaGetSymbolAddress((void**)&qbf,    g_qbf);
    cudaGetSymbolAddress((void**)&fbf,    g_fbf);
    cudaGetSymbolAddress((void**)&val_s,  g_value);
    cudaGetSymbolAddress((void**)&off_s,  g_off);
    cudaGetSymbolAddress((void**)&al_s,   g_attnlog);
    cudaGetSymbolAddress((void**)&sampb,  g_sampb);
    cudaGetSymbolAddress((void**)&attn_s, g_attn);
    cudaGetSymbolAddress((void**)&dest_s, g_dest);
    cudaGetSymbolAddress((void**)&wvalT,  g_wvalT);
    cudaGetSymbolAddress((void**)&woutT,  g_woutT);
    cudaGetSymbolAddress((void**)&woffT,  g_woffT);
    cudaGetSymbolAddress((void**)&wattnT, g_wattnT);

    // weight transposes ([K,N] f32 -> [Npad,K] bf16, zero-padded)
    transpose_pad<<<dim3(3, DMODEL), 256>>>(W_val,  wvalT,  DMODEL,   DMODEL);
    transpose_pad<<<dim3(3, OFF_LD), 256>>>(W_off,  woffT,  OFFCOLS,  OFF_LD);
    transpose_pad<<<dim3(3, ATT_LD), 256>>>(W_attn, wattnT, ATTNCOLS, ATT_LD);
    transpose_pad<<<dim3(3, DMODEL), 256>>>(W_out,  woutT,  DMODEL,   DMODEL);

    ln_kernel<<<NQROWS, 256>>>(query, ln_q_s, ln_q_b, qbf);
    ln_kernel<<<NFROWS, 256>>>(feat,  ln_f_s, ln_f_b, fbf);

    // value = f @ W_val + b_val   (43008 x 768 x 768)
    mma_gemm<<<dim3(6, NFROWS / 128), 256>>>(fbf, wvalT, b_val, val_s, DMODEL, DMODEL);
    // off = q @ W_off + b_off     (8192 x 144 x 768), padded ldc=256
    mma_gemm<<<dim3(2, NQROWS / 128), 256>>>(qbf, woffT, b_off, off_s, OFFCOLS, OFF_LD);
    // attn logits = q @ W_attn    (8192 x 72 x 768), padded ldc=128
    mma_gemm<<<dim3(1, NQROWS / 128), 256>>>(qbf, wattnT, b_attn, al_s, ATTNCOLS, ATT_LD);

    msda_sample_kernel<<<NQROWS, 128>>>(off_s, al_s, val_s, sampb);

    // attn = samp @ W_out + b_out (8192 x 768 x 768)
    mma_gemm<<<dim3(6, NQROWS / 128), 256>>>(sampb, woutT, b_out, attn_s, DMODEL, DMODEL);

    dest_kernel<<<BATCH, 1024>>>(mask, dest_s);
    final_kernel<<<NQROWS, 256>>>(query, gamma, attn_s, dest_s, out);
}